// round 4
// baseline (speedup 1.0000x reference)
#include <cuda_runtime.h>
#include <math.h>
#include <stdint.h>

// Fixed problem shapes
#define BB   4
#define SS   2048
#define GG   8
#define DD   128
#define NN   64
#define BG   (BB*GG)          // 32
#define NTOK (BB*SS*GG)       // 65536
#define SUB  32
#define NSUB (SS/SUB)         // 64

typedef unsigned long long ull;

// Scratch (device globals; no allocation allowed)
__device__ float4 g_hc[BG*SS*NN];      // (hl_r, hl_i, c_r, c_i)  64 MB
__device__ float2 g_hin[BG*NSUB*NN];   // subchunk input states    1 MB

// ---------------- f32x2 helpers ----------------
__device__ __forceinline__ void fma2(ull& d, ull a, ull b) {
    asm("fma.rn.f32x2 %0, %1, %2, %0;" : "+l"(d) : "l"(a), "l"(b));
}
__device__ __forceinline__ ull neg2(ull v) { return v ^ 0x8000000080000000ULL; }
__device__ __forceinline__ float comp(ull v, int e) {
    float x, y;
    asm("mov.b64 {%0, %1}, %2;" : "=f"(x), "=f"(y) : "l"(v));
    return e ? y : x;
}
__device__ __forceinline__ float warpsum(float v) {
    #pragma unroll
    for (int off = 16; off; off >>= 1) v += __shfl_xor_sync(0xffffffffu, v, off);
    return v;
}
__device__ __forceinline__ float clampdt(float v) {
    return fminf(fmaxf(v, 1e-4f), 2.0f);
}

// ---------------------------------------------------------------------------
// Kernel 1 (fused projection + local scan). Grid = 512: blockIdx>>8 selects the
// n-half (32 states) this CTA owns; weights live in smem as duplicated (w,w)
// pairs so the FFMA2 inner loop has ZERO operand movs. Each warp owns one
// (bg, subchunk) slice of 32 tokens; lane owns one state n.
// ---------------------------------------------------------------------------
__global__ __launch_bounds__(256, 2) void k1_scan(
    const float* __restrict__ xr_g, const float* __restrict__ xi_g,
    const float* __restrict__ logA, const float* __restrict__ Aph_g,
    const float* __restrict__ Bwr,  const float* __restrict__ Bwi,
    const float* __restrict__ dtw_g, const float* __restrict__ dtb_g)
{
    extern __shared__ float sm[];
    float2* wr2 = (float2*)sm;             // [128 d][32 n] (w,w)  32 KB
    float2* wi2 = wr2 + 128*32;            // 32 KB
    float*  dtw = (float*)(wi2 + 128*32);  // 512
    float*  nlA = dtw + 512;               // 512
    float*  aph = nlA + 512;               // 512
    float2* xbase = (float2*)(aph + 512);  // 8 warps * 512 float2 (32 KB)

    const int tid = threadIdx.x;
    const int half = blockIdx.x >> 8;      // n-half this CTA owns
    const int nb = half * 32;

    for (int i = tid; i < 128*32; i += 256) {
        int d = i >> 5, nl = i & 31;
        float wr = Bwr[(nb + nl)*DD + d];
        float wi = Bwi[(nb + nl)*DD + d];
        wr2[d*32 + nl] = make_float2(wr, wr);
        wi2[d*32 + nl] = make_float2(wi, wi);
    }
    for (int i = tid; i < 512; i += 256) {
        dtw[i] = dtw_g[i];
        nlA[i] = -log1pf(expf(logA[i]));   // -softplus
        aph[i] = Aph_g[i];
    }
    __syncthreads();

    const int w = tid >> 5, l = tid & 31;
    const int slice = (blockIdx.x & 255)*8 + w;   // 0..2047
    const int bg = slice >> 6, sub = slice & 63;
    const int b = bg >> 3, g = bg & 7;
    float2* xpr = xbase + w*512;           // [2 t-pairs][128 d] interleaved
    float2* xpi = xpr + 256;
    const float db0 = dtb_g[0], db1 = dtb_g[1];
    const float m_nlA = nlA[g*64 + nb + l];
    const float m_aph = aph[g*64 + nb + l];

    float hr = 0.f, hi = 0.f, cr = 1.f, ci = 0.f;

    for (int pass = 0; pass < 8; ++pass) {
        const int s0 = sub*SUB + pass*4;
        const int t0 = (b*SS + s0)*GG + g;     // tokens stride GG in memory

        // ---- stage x token-pair interleaved ----
        #pragma unroll
        for (int p = 0; p < 2; ++p) {
            int ta = t0 + 2*p*GG, tb = ta + GG;
            float4 r0 = ((const float4*)(xr_g + (size_t)ta*DD))[l];
            float4 r1 = ((const float4*)(xr_g + (size_t)tb*DD))[l];
            float4 i0 = ((const float4*)(xi_g + (size_t)ta*DD))[l];
            float4 i1 = ((const float4*)(xi_g + (size_t)tb*DD))[l];
            float2* xp = xpr + p*128;
            *(float4*)&xp[4*l]     = make_float4(r0.x, r1.x, r0.y, r1.y);
            *(float4*)&xp[4*l + 2] = make_float4(r0.z, r1.z, r0.w, r1.w);
            float2* xq = xpi + p*128;
            *(float4*)&xq[4*l]     = make_float4(i0.x, i1.x, i0.y, i1.y);
            *(float4*)&xq[4*l + 2] = make_float4(i0.z, i1.z, i0.w, i1.w);
        }
        __syncwarp();

        // ---- dt logits ----
        float dm[4], dp[4];
        #pragma unroll
        for (int p = 0; p < 2; ++p) {
            float a0x=0.f, a0y=0.f, a1x=0.f, a1y=0.f;
            #pragma unroll
            for (int k = 0; k < 4; ++k) {
                int d = l + 32*k;
                float2 xr = xpr[p*128 + d];
                float2 xi = xpi[p*128 + d];
                float w0r = dtw[d], w0i = dtw[128 + d];
                float w1r = dtw[256 + d], w1i = dtw[384 + d];
                a0x = fmaf(xr.x, w0r, fmaf(xi.x, w0i, a0x));
                a0y = fmaf(xr.y, w0r, fmaf(xi.y, w0i, a0y));
                a1x = fmaf(xr.x, w1r, fmaf(xi.x, w1i, a1x));
                a1y = fmaf(xr.y, w1r, fmaf(xi.y, w1i, a1y));
            }
            a0x = warpsum(a0x); a0y = warpsum(a0y);
            a1x = warpsum(a1x); a1y = warpsum(a1y);
            dm[2*p]   = clampdt(__expf(a0x + db0));
            dm[2*p+1] = clampdt(__expf(a0y + db0));
            dp[2*p]   = clampdt(__expf(a1x + db1));
            dp[2*p+1] = clampdt(__expf(a1y + db1));
        }

        // ---- FFMA2 complex B projection: zero-mov inner loop ----
        ull aR[2] = {0, 0}, aI[2] = {0, 0};   // per token-pair, lane's n

        #pragma unroll 4
        for (int d = 0; d < 128; d += 2) {
            ull wra  = *(const ull*)&wr2[d*32 + l];
            ull wrb  = *(const ull*)&wr2[(d+1)*32 + l];
            ull wia  = *(const ull*)&wi2[d*32 + l];
            ull wib  = *(const ull*)&wi2[(d+1)*32 + l];
            ull nwia = neg2(wia), nwib = neg2(wib);
            #pragma unroll
            for (int p = 0; p < 2; ++p) {
                ulonglong2 xr = *(const ulonglong2*)(xpr + p*128 + d);
                ulonglong2 xi = *(const ulonglong2*)(xpi + p*128 + d);
                fma2(aR[p], xr.x, wra);  fma2(aR[p], xi.x, nwia);
                fma2(aI[p], xr.x, wia);  fma2(aI[p], xi.x, wra);
                fma2(aR[p], xr.y, wrb);  fma2(aR[p], xi.y, nwib);
                fma2(aI[p], xr.y, wib);  fma2(aI[p], xi.y, wrb);
            }
        }

        // ---- local scan + store (h_local, cumprod) for lane's n ----
        #pragma unroll
        for (int j = 0; j < 4; ++j) {
            const int p = j >> 1, e = j & 1;
            const int s = s0 + j;
            const float dmv = dm[j], dpv = dp[j];
            float am = __expf(dmv * m_nlA);
            float sn, cs;
            __sincosf(dpv * m_aph, &sn, &cs);
            float ar = am*cs, ai = am*sn;
            float br = comp(aR[p], e) * dmv;
            float bi = comp(aI[p], e) * dmv;
            float nhr = fmaf(ar, hr, fmaf(-ai, hi, br));
            float nhi = fmaf(ar, hi, fmaf( ai, hr, bi));
            float ncr = ar*cr - ai*ci;
            float nci = ar*ci + ai*cr;
            hr = nhr; hi = nhi; cr = ncr; ci = nci;
            g_hc[((size_t)bg*SS + s)*NN + nb + l] = make_float4(nhr, nhi, ncr, nci);
        }
        __syncwarp();
    }
}

// ---------------------------------------------------------------------------
// Kernel 2b: sequential subchunk combine; renorm every 8th subchunk boundary.
// ---------------------------------------------------------------------------
__global__ __launch_bounds__(64) void k2b_combine(void)
{
    int bg = blockIdx.x;
    int n = threadIdx.x;
    float hr = 0.f, hi = 0.f;

    float4 ebuf[8];
    #pragma unroll
    for (int j = 0; j < 8; ++j)
        ebuf[j] = g_hc[((size_t)bg*SS + j*SUB + 31)*NN + n];

    for (int s0 = 0; s0 < NSUB; s0 += 8) {
        #pragma unroll
        for (int j = 0; j < 8; ++j) {
            float4 e = ebuf[j];
            int nsub = s0 + 8 + j;
            if (nsub < NSUB)
                ebuf[j] = g_hc[((size_t)bg*SS + nsub*SUB + 31)*NN + n];
            int sub = s0 + j;
            g_hin[(bg*NSUB + sub)*NN + n] = make_float2(hr, hi);
            float nr = fmaf(e.z, hr, fmaf(-e.w, hi, e.x));
            float ni = fmaf(e.z, hi, fmaf( e.w, hr, e.y));
            if ((sub & 7) == 7) {
                float nm = sqrtf(nr*nr + ni*ni + 1e-8f);
                float sc = fminf(nm, 100.0f)/nm;
                nr *= sc; ni *= sc;
            }
            hr = nr; hi = ni;
        }
    }
}

// ---------------------------------------------------------------------------
// Kernel 3: correction h = h_local + c*h_in (+renorm) fused with complex C
// projection. f32x2 packed over OUTPUT d (lane owns d=2l,2l+1,2l+64,2l+65):
// weight pairs are natural LDS.64 from [n][d] layout (no movs); h staged
// duplicated (h,h) in smem, LDS.64 broadcast; -ci once per n.
// ---------------------------------------------------------------------------
__global__ __launch_bounds__(256, 2) void k3_out(
    const float* __restrict__ Cwr, const float* __restrict__ Cwi,
    float* __restrict__ out)
{
    extern __shared__ float sm[];
    float* crr = sm;                 // [n][d] 8192 floats (32 KB)
    float* cii = crr + 8192;         // 32 KB
    float2* hbase = (float2*)(cii + 8192);  // 8 warps * 512 float2 (32 KB)

    const int tid = threadIdx.x;
    for (int i = tid; i < 8192; i += 256) {
        int d = i & 127, n = i >> 7;
        crr[n*128 + d] = Cwr[d*64 + n];
        cii[n*128 + d] = Cwi[d*64 + n];
    }
    __syncthreads();

    const int w = tid >> 5, l = tid & 31;
    float2* hrp = hbase + w*512;     // [4 tok][64 n] duplicated (h,h)
    float2* hip = hrp + 256;
    const size_t OFF = (size_t)NTOK*DD;

    for (int grp = blockIdx.x; grp < NTOK/32; grp += gridDim.x) {
        const int tbase = grp*32 + w*4;

        // ---- stage corrected h as duplicated pairs ----
        #pragma unroll
        for (int k = 0; k < 4; ++k) {
            int t = tbase + k;
            int b = t >> 14, g = t & 7, s = (t >> 3) & 2047;
            int bg = b*GG + g;
            size_t idx = ((size_t)bg*SS + s)*NN;
            int hini = (bg*NSUB + (s >> 5))*NN;
            #pragma unroll
            for (int ns = 0; ns < 2; ++ns) {
                int n = l + 32*ns;
                float4 hc = g_hc[idx + n];
                float2 hin = g_hin[hini + n];
                float hrv = fmaf(hc.z, hin.x, fmaf(-hc.w, hin.y, hc.x));
                float hiv = fmaf(hc.z, hin.y, fmaf( hc.w, hin.x, hc.y));
                if ((s & 255) == 255) {
                    float nm = sqrtf(hrv*hrv + hiv*hiv + 1e-8f);
                    float sc = fminf(nm, 100.0f)/nm;
                    hrv *= sc; hiv *= sc;
                }
                hrp[k*64 + n] = make_float2(hrv, hrv);
                hip[k*64 + n] = make_float2(hiv, hiv);
            }
        }
        __syncwarp();

        // ---- FFMA2 C projection, packed over d ----
        ull yR0[4] = {0,0,0,0}, yR1[4] = {0,0,0,0};
        ull yI0[4] = {0,0,0,0}, yI1[4] = {0,0,0,0};

        #pragma unroll 2
        for (int n = 0; n < NN; ++n) {
            ull cr0 = *(const ull*)&crr[n*128 + 2*l];        // (c[2l],c[2l+1])
            ull cr1 = *(const ull*)&crr[n*128 + 2*l + 64];
            ull ci0 = *(const ull*)&cii[n*128 + 2*l];
            ull ci1 = *(const ull*)&cii[n*128 + 2*l + 64];
            ull nci0 = neg2(ci0), nci1 = neg2(ci1);
            #pragma unroll
            for (int t = 0; t < 4; ++t) {
                ull hr = *(const ull*)&hrp[t*64 + n];        // broadcast
                ull hi = *(const ull*)&hip[t*64 + n];
                fma2(yR0[t], hr, cr0);  fma2(yR0[t], hi, nci0);
                fma2(yI0[t], hr, ci0);  fma2(yI0[t], hi, cr0);
                fma2(yR1[t], hr, cr1);  fma2(yR1[t], hi, nci1);
                fma2(yI1[t], hr, ci1);  fma2(yI1[t], hi, cr1);
            }
        }

        // ---- output: each ull is a float2 of adjacent d ----
        #pragma unroll
        for (int t = 0; t < 4; ++t) {
            size_t o = (size_t)(tbase + t)*DD + 2*l;
            *(ull*)(out + o)            = yR0[t];
            *(ull*)(out + o + 64)       = yR1[t];
            *(ull*)(out + OFF + o)      = yI0[t];
            *(ull*)(out + OFF + o + 64) = yI1[t];
        }
        __syncwarp();
    }
}

// ---------------------------------------------------------------------------
extern "C" void kernel_launch(void* const* d_in, const int* in_sizes, int n_in,
                              void* d_out, int out_size)
{
    const float* x_r  = (const float*)d_in[0];
    const float* x_i  = (const float*)d_in[1];
    const float* logA = (const float*)d_in[2];
    const float* Aph  = (const float*)d_in[3];
    const float* Bwr  = (const float*)d_in[4];
    const float* Bwi  = (const float*)d_in[5];
    const float* Cwr  = (const float*)d_in[6];
    const float* Cwi  = (const float*)d_in[7];
    const float* dtw  = (const float*)d_in[8];
    const float* dtb  = (const float*)d_in[9];
    float* out = (float*)d_out;

    const int smem1 = (128*32*2*2 + 512*3 + 8*512*2) * 4;  // 104448 B
    const int smem3 = (8192*2 + 8*512*2) * 4;              // 98304 B
    cudaFuncSetAttribute(k1_scan, cudaFuncAttributeMaxDynamicSharedMemorySize, smem1);
    cudaFuncSetAttribute(k3_out,  cudaFuncAttributeMaxDynamicSharedMemorySize, smem3);

    k1_scan<<<512, 256, smem1>>>(x_r, x_i, logA, Aph, Bwr, Bwi, dtw, dtb);
    k2b_combine<<<BG, 64>>>();
    k3_out<<<296, 256, smem3>>>(Cwr, Cwi, out);
}

// round 5
// speedup vs baseline: 1.2959x; 1.2959x over previous
#include <cuda_runtime.h>
#include <math.h>
#include <stdint.h>

// Fixed problem shapes
#define BB   4
#define SS   2048
#define GG   8
#define DD   128
#define NN   64
#define BG   (BB*GG)          // 32
#define NTOK (BB*SS*GG)       // 65536
#define SUB  32
#define NSUB (SS/SUB)         // 64
#define NSLICE (BG*NSUB)      // 2048

typedef unsigned long long ull;

// Scratch (device globals; no allocation allowed)
__device__ float4 g_hc[BG*SS*NN];      // (hl_r, hl_i, c_r, c_i)  64 MB
__device__ float2 g_hin[BG*NSUB*NN];   // subchunk input states    1 MB

// ---------------- f32x2 helpers ----------------
__device__ __forceinline__ ull pk(float x, float y) {
    ull r; asm("mov.b64 %0, {%1, %2};" : "=l"(r) : "f"(x), "f"(y)); return r;
}
__device__ __forceinline__ void fma2(ull& d, ull a, ull b) {
    asm("fma.rn.f32x2 %0, %1, %2, %0;" : "+l"(d) : "l"(a), "l"(b));
}
__device__ __forceinline__ ull neg2(ull v) { return v ^ 0x8000000080000000ULL; }
__device__ __forceinline__ float comp(ull v, int e) {
    float x, y;
    asm("mov.b64 {%0, %1}, %2;" : "=f"(x), "=f"(y) : "l"(v));
    return e ? y : x;
}
__device__ __forceinline__ float warpsum(float v) {
    #pragma unroll
    for (int off = 16; off; off >>= 1) v += __shfl_xor_sync(0xffffffffu, v, off);
    return v;
}
__device__ __forceinline__ float clampdt(float v) {
    return fminf(fmaxf(v, 1e-4f), 2.0f);
}

// ---------------------------------------------------------------------------
// Kernel 1 (fused projection + local scan). Grid 296, 7 slices per CTA
// (warps 0-6 work, warp 7 idles) -> every SM carries exactly 14 slices.
// Warp owns one (bg, subchunk) slice of 32 tokens; lane owns states l, l+32.
// Weights (wr,wi) packed in smem [d][n]; x register-prefetched per pass and
// staged token-pair interleaved; inner loop = FFMA2 with LDS.64/LDS.128 only.
// ---------------------------------------------------------------------------
__global__ __launch_bounds__(256, 2) void k1_scan(
    const float* __restrict__ xr_g, const float* __restrict__ xi_g,
    const float* __restrict__ logA, const float* __restrict__ Aph_g,
    const float* __restrict__ Bwr,  const float* __restrict__ Bwi,
    const float* __restrict__ dtw_g, const float* __restrict__ dtb_g)
{
    extern __shared__ float sm[];
    float2* wrwi = (float2*)sm;            // [128 d][64 n] (wr,wi)  64 KB
    float*  dtw  = (float*)(wrwi + 8192);  // 512
    float*  nlA  = dtw + 512;              // 512
    float*  aph  = nlA + 512;              // 512
    float2* xbase = (float2*)(aph + 512);  // 8 warps * 512 float2 (32 KB)

    const int tid = threadIdx.x;
    for (int i = tid; i < 8192; i += 256) {
        int d = i >> 6, n = i & 63;
        wrwi[d*64 + n] = make_float2(Bwr[n*128 + d], Bwi[n*128 + d]);
    }
    for (int i = tid; i < 512; i += 256) {
        dtw[i] = dtw_g[i];
        nlA[i] = -log1pf(expf(logA[i]));   // -softplus
        aph[i] = Aph_g[i];
    }
    __syncthreads();

    const int w = tid >> 5, l = tid & 31;
    const int slice = blockIdx.x*7 + w;    // 7 working warps per CTA
    if (w == 7 || slice >= NSLICE) return;
    const int bg = slice >> 6, sub = slice & 63;
    const int b = bg >> 3, g = bg & 7;
    float2* xpr = xbase + w*512;           // [2 t-pairs][128 d] interleaved
    float2* xpi = xpr + 256;
    const float db0 = dtb_g[0], db1 = dtb_g[1];
    const float nlA0 = nlA[g*64 + l],      aph0 = aph[g*64 + l];
    const float nlA1 = nlA[g*64 + l + 32], aph1 = aph[g*64 + l + 32];

    float hr0=0.f, hi0=0.f, cr0=1.f, ci0=0.f;
    float hr1=0.f, hi1=0.f, cr1=1.f, ci1=0.f;

    // prefetch pass 0 x into registers
    float4 pfr[4], pfi[4];
    {
        const int t0 = (b*SS + sub*SUB)*GG + g;
        #pragma unroll
        for (int k = 0; k < 4; ++k) {
            pfr[k] = ((const float4*)(xr_g + (size_t)(t0 + k*GG)*DD))[l];
            pfi[k] = ((const float4*)(xi_g + (size_t)(t0 + k*GG)*DD))[l];
        }
    }

    for (int pass = 0; pass < 8; ++pass) {
        // ---- stage prefetched x token-pair interleaved ----
        #pragma unroll
        for (int p = 0; p < 2; ++p) {
            float4 r0 = pfr[2*p], r1 = pfr[2*p+1];
            float4 i0 = pfi[2*p], i1 = pfi[2*p+1];
            float2* xp = xpr + p*128;
            *(float4*)&xp[4*l]     = make_float4(r0.x, r1.x, r0.y, r1.y);
            *(float4*)&xp[4*l + 2] = make_float4(r0.z, r1.z, r0.w, r1.w);
            float2* xq = xpi + p*128;
            *(float4*)&xq[4*l]     = make_float4(i0.x, i1.x, i0.y, i1.y);
            *(float4*)&xq[4*l + 2] = make_float4(i0.z, i1.z, i0.w, i1.w);
        }
        __syncwarp();

        // ---- prefetch next pass (overlaps with compute below) ----
        if (pass < 7) {
            const int t0 = (b*SS + sub*SUB + (pass+1)*4)*GG + g;
            #pragma unroll
            for (int k = 0; k < 4; ++k) {
                pfr[k] = ((const float4*)(xr_g + (size_t)(t0 + k*GG)*DD))[l];
                pfi[k] = ((const float4*)(xi_g + (size_t)(t0 + k*GG)*DD))[l];
            }
        }

        // ---- dt logits ----
        float dm[4], dp[4];
        #pragma unroll
        for (int p = 0; p < 2; ++p) {
            float a0x=0.f, a0y=0.f, a1x=0.f, a1y=0.f;
            #pragma unroll
            for (int k = 0; k < 4; ++k) {
                int d = l + 32*k;
                float2 xr = xpr[p*128 + d];
                float2 xi = xpi[p*128 + d];
                float w0r = dtw[d], w0i = dtw[128 + d];
                float w1r = dtw[256 + d], w1i = dtw[384 + d];
                a0x = fmaf(xr.x, w0r, fmaf(xi.x, w0i, a0x));
                a0y = fmaf(xr.y, w0r, fmaf(xi.y, w0i, a0y));
                a1x = fmaf(xr.x, w1r, fmaf(xi.x, w1i, a1x));
                a1y = fmaf(xr.y, w1r, fmaf(xi.y, w1i, a1y));
            }
            a0x = warpsum(a0x); a0y = warpsum(a0y);
            a1x = warpsum(a1x); a1y = warpsum(a1y);
            dm[2*p]   = clampdt(__expf(a0x + db0));
            dm[2*p+1] = clampdt(__expf(a0y + db0));
            dp[2*p]   = clampdt(__expf(a1x + db1));
            dp[2*p+1] = clampdt(__expf(a1y + db1));
        }

        // ---- FFMA2 complex B projection ----
        ull aR[2][2] = {{0,0},{0,0}}, aI[2][2] = {{0,0},{0,0}};

        #pragma unroll 8
        for (int d = 0; d < 128; d += 2) {
            float2 wa0 = wrwi[d*64 + l];          // (wr,wi) n=l,    depth d
            float2 wb0 = wrwi[d*64 + l + 32];     // n=l+32, depth d
            float2 wa1 = wrwi[(d+1)*64 + l];
            float2 wb1 = wrwi[(d+1)*64 + l + 32];
            ull ra0 = pk(wa0.x, wa0.x), ia0 = pk(wa0.y, wa0.y);
            ull rb0 = pk(wb0.x, wb0.x), ib0 = pk(wb0.y, wb0.y);
            ull ra1 = pk(wa1.x, wa1.x), ia1 = pk(wa1.y, wa1.y);
            ull rb1 = pk(wb1.x, wb1.x), ib1 = pk(wb1.y, wb1.y);
            ull na0 = neg2(ia0), nb0 = neg2(ib0);
            ull na1 = neg2(ia1), nb1 = neg2(ib1);
            #pragma unroll
            for (int p = 0; p < 2; ++p) {
                ulonglong2 xr = *(const ulonglong2*)(xpr + p*128 + d);
                ulonglong2 xi = *(const ulonglong2*)(xpi + p*128 + d);
                fma2(aR[p][0], xr.x, ra0);  fma2(aR[p][0], xi.x, na0);
                fma2(aI[p][0], xr.x, ia0);  fma2(aI[p][0], xi.x, ra0);
                fma2(aR[p][1], xr.x, rb0);  fma2(aR[p][1], xi.x, nb0);
                fma2(aI[p][1], xr.x, ib0);  fma2(aI[p][1], xi.x, rb0);
                fma2(aR[p][0], xr.y, ra1);  fma2(aR[p][0], xi.y, na1);
                fma2(aI[p][0], xr.y, ia1);  fma2(aI[p][0], xi.y, ra1);
                fma2(aR[p][1], xr.y, rb1);  fma2(aR[p][1], xi.y, nb1);
                fma2(aI[p][1], xr.y, ib1);  fma2(aI[p][1], xi.y, rb1);
            }
        }

        // ---- in-register local scan + store (h_local, cumprod) ----
        const int s0 = sub*SUB + pass*4;
        #pragma unroll
        for (int j = 0; j < 4; ++j) {
            const int p = j >> 1, e = j & 1;
            const float dmv = dm[j], dpv = dp[j];
            const size_t idx = ((size_t)bg*SS + (s0 + j))*NN;
            // slot 0 (n = l)
            {
                float am = __expf(dmv * nlA0);
                float sn, cs; __sincosf(dpv * aph0, &sn, &cs);
                float ar = am*cs, ai = am*sn;
                float br = comp(aR[p][0], e) * dmv;
                float bi = comp(aI[p][0], e) * dmv;
                float nhr = fmaf(ar, hr0, fmaf(-ai, hi0, br));
                float nhi = fmaf(ar, hi0, fmaf( ai, hr0, bi));
                float ncr = ar*cr0 - ai*ci0;
                float nci = ar*ci0 + ai*cr0;
                hr0 = nhr; hi0 = nhi; cr0 = ncr; ci0 = nci;
                g_hc[idx + l] = make_float4(nhr, nhi, ncr, nci);
            }
            // slot 1 (n = l + 32)
            {
                float am = __expf(dmv * nlA1);
                float sn, cs; __sincosf(dpv * aph1, &sn, &cs);
                float ar = am*cs, ai = am*sn;
                float br = comp(aR[p][1], e) * dmv;
                float bi = comp(aI[p][1], e) * dmv;
                float nhr = fmaf(ar, hr1, fmaf(-ai, hi1, br));
                float nhi = fmaf(ar, hi1, fmaf( ai, hr1, bi));
                float ncr = ar*cr1 - ai*ci1;
                float nci = ar*ci1 + ai*cr1;
                hr1 = nhr; hi1 = nhi; cr1 = ncr; ci1 = nci;
                g_hc[idx + l + 32] = make_float4(nhr, nhi, ncr, nci);
            }
        }
        __syncwarp();
    }
}

// ---------------------------------------------------------------------------
// Kernel 2b: sequential subchunk combine; renorm every 8th subchunk boundary.
// ---------------------------------------------------------------------------
__global__ __launch_bounds__(64) void k2b_combine(void)
{
    int bg = blockIdx.x;
    int n = threadIdx.x;
    float hr = 0.f, hi = 0.f;

    float4 ebuf[8];
    #pragma unroll
    for (int j = 0; j < 8; ++j)
        ebuf[j] = g_hc[((size_t)bg*SS + j*SUB + 31)*NN + n];

    for (int s0 = 0; s0 < NSUB; s0 += 8) {
        #pragma unroll
        for (int j = 0; j < 8; ++j) {
            float4 e = ebuf[j];
            int nsub = s0 + 8 + j;
            if (nsub < NSUB)
                ebuf[j] = g_hc[((size_t)bg*SS + nsub*SUB + 31)*NN + n];
            int sub = s0 + j;
            g_hin[(bg*NSUB + sub)*NN + n] = make_float2(hr, hi);
            float nr = fmaf(e.z, hr, fmaf(-e.w, hi, e.x));
            float ni = fmaf(e.z, hi, fmaf( e.w, hr, e.y));
            if ((sub & 7) == 7) {
                float nm = sqrtf(nr*nr + ni*ni + 1e-8f);
                float sc = fminf(nm, 100.0f)/nm;
                nr *= sc; ni *= sc;
            }
            hr = nr; hi = ni;
        }
    }
}

// ---------------------------------------------------------------------------
// Kernel 3: correction h = h_local + c*h_in (+renorm) fused with complex C
// projection. f32x2 packed over OUTPUT d; weight pairs natural LDS.64; h
// staged duplicated (h,h); g_hc register-prefetched per group.
// ---------------------------------------------------------------------------
__global__ __launch_bounds__(256, 2) void k3_out(
    const float* __restrict__ Cwr, const float* __restrict__ Cwi,
    float* __restrict__ out)
{
    extern __shared__ float sm[];
    float* crr = sm;                 // [n][d] 8192 floats (32 KB)
    float* cii = crr + 8192;         // 32 KB
    float2* hbase = (float2*)(cii + 8192);  // 8 warps * 512 float2 (32 KB)

    const int tid = threadIdx.x;
    for (int i = tid; i < 8192; i += 256) {
        int d = i & 127, n = i >> 7;
        crr[n*128 + d] = Cwr[d*64 + n];
        cii[n*128 + d] = Cwi[d*64 + n];
    }
    __syncthreads();

    const int w = tid >> 5, l = tid & 31;
    float2* hrp = hbase + w*512;     // [4 tok][64 n] duplicated (h,h)
    float2* hip = hrp + 256;
    const size_t OFF = (size_t)NTOK*DD;

    // prefetch first group's hc
    float4 pf[8];
    int grp = blockIdx.x;
    if (grp < NTOK/32) {
        #pragma unroll
        for (int k = 0; k < 4; ++k) {
            int t = grp*32 + w*4 + k;
            int b = t >> 14, g = t & 7, s = (t >> 3) & 2047;
            size_t idx = ((size_t)(b*GG + g)*SS + s)*NN;
            pf[2*k]   = g_hc[idx + l];
            pf[2*k+1] = g_hc[idx + l + 32];
        }
    }

    for (; grp < NTOK/32; grp += gridDim.x) {
        const int tbase = grp*32 + w*4;

        // ---- stage corrected h as duplicated pairs ----
        #pragma unroll
        for (int k = 0; k < 4; ++k) {
            int t = tbase + k;
            int b = t >> 14, g = t & 7, s = (t >> 3) & 2047;
            int bg = b*GG + g;
            int hini = (bg*NSUB + (s >> 5))*NN;
            bool renorm = ((s & 255) == 255);
            #pragma unroll
            for (int ns = 0; ns < 2; ++ns) {
                int n = l + 32*ns;
                float4 hc = pf[2*k + ns];
                float2 hin = g_hin[hini + n];
                float hrv = fmaf(hc.z, hin.x, fmaf(-hc.w, hin.y, hc.x));
                float hiv = fmaf(hc.z, hin.y, fmaf( hc.w, hin.x, hc.y));
                if (renorm) {
                    float nm = sqrtf(hrv*hrv + hiv*hiv + 1e-8f);
                    float sc = fminf(nm, 100.0f)/nm;
                    hrv *= sc; hiv *= sc;
                }
                hrp[k*64 + n] = make_float2(hrv, hrv);
                hip[k*64 + n] = make_float2(hiv, hiv);
            }
        }
        __syncwarp();

        // ---- prefetch next group's hc (overlaps compute) ----
        int ngrp = grp + gridDim.x;
        if (ngrp < NTOK/32) {
            #pragma unroll
            for (int k = 0; k < 4; ++k) {
                int t = ngrp*32 + w*4 + k;
                int b = t >> 14, g = t & 7, s = (t >> 3) & 2047;
                size_t idx = ((size_t)(b*GG + g)*SS + s)*NN;
                pf[2*k]   = g_hc[idx + l];
                pf[2*k+1] = g_hc[idx + l + 32];
            }
        }

        // ---- FFMA2 C projection, packed over d ----
        ull yR0[4] = {0,0,0,0}, yR1[4] = {0,0,0,0};
        ull yI0[4] = {0,0,0,0}, yI1[4] = {0,0,0,0};

        #pragma unroll 4
        for (int n = 0; n < NN; ++n) {
            ull cr0 = *(const ull*)&crr[n*128 + 2*l];        // (c[2l],c[2l+1])
            ull cr1 = *(const ull*)&crr[n*128 + 2*l + 64];
            ull ci0 = *(const ull*)&cii[n*128 + 2*l];
            ull ci1 = *(const ull*)&cii[n*128 + 2*l + 64];
            ull nci0 = neg2(ci0), nci1 = neg2(ci1);
            #pragma unroll
            for (int t = 0; t < 4; ++t) {
                ull hr = *(const ull*)&hrp[t*64 + n];        // broadcast
                ull hi = *(const ull*)&hip[t*64 + n];
                fma2(yR0[t], hr, cr0);  fma2(yR0[t], hi, nci0);
                fma2(yI0[t], hr, ci0);  fma2(yI0[t], hi, cr0);
                fma2(yR1[t], hr, cr1);  fma2(yR1[t], hi, nci1);
                fma2(yI1[t], hr, ci1);  fma2(yI1[t], hi, cr1);
            }
        }

        // ---- output: each ull is a float2 of adjacent d ----
        #pragma unroll
        for (int t = 0; t < 4; ++t) {
            size_t o = (size_t)(tbase + t)*DD + 2*l;
            *(ull*)(out + o)            = yR0[t];
            *(ull*)(out + o + 64)       = yR1[t];
            *(ull*)(out + OFF + o)      = yI0[t];
            *(ull*)(out + OFF + o + 64) = yI1[t];
        }
        __syncwarp();
    }
}

// ---------------------------------------------------------------------------
extern "C" void kernel_launch(void* const* d_in, const int* in_sizes, int n_in,
                              void* d_out, int out_size)
{
    const float* x_r  = (const float*)d_in[0];
    const float* x_i  = (const float*)d_in[1];
    const float* logA = (const float*)d_in[2];
    const float* Aph  = (const float*)d_in[3];
    const float* Bwr  = (const float*)d_in[4];
    const float* Bwi  = (const float*)d_in[5];
    const float* Cwr  = (const float*)d_in[6];
    const float* Cwi  = (const float*)d_in[7];
    const float* dtw  = (const float*)d_in[8];
    const float* dtb  = (const float*)d_in[9];
    float* out = (float*)d_out;

    const int smem1 = (8192*2 + 512*3 + 8*512*2) * 4;  // 104448 B
    const int smem3 = (8192*2 + 8*512*2) * 4;          // 98304 B
    cudaFuncSetAttribute(k1_scan, cudaFuncAttributeMaxDynamicSharedMemorySize, smem1);
    cudaFuncSetAttribute(k3_out,  cudaFuncAttributeMaxDynamicSharedMemorySize, smem3);

    k1_scan<<<296, 256, smem1>>>(x_r, x_i, logA, Aph, Bwr, Bwi, dtw, dtb);
    k2b_combine<<<BG, 64>>>();
    k3_out<<<296, 256, smem3>>>(Cwr, Cwi, out);
}

// round 6
// speedup vs baseline: 1.3026x; 1.0052x over previous
#include <cuda_runtime.h>
#include <math.h>
#include <stdint.h>

// Fixed problem shapes
#define BB   4
#define SS   2048
#define GG   8
#define DD   128
#define NN   64
#define BG   (BB*GG)          // 32
#define NTOK (BB*SS*GG)       // 65536
#define SUB  32
#define NSUB (SS/SUB)         // 64
#define NSLICE (BG*NSUB)      // 2048

typedef unsigned long long ull;

// Scratch (device globals; no allocation allowed)
__device__ float4 g_hc[BG*SS*NN];      // (hl_r, hl_i, c_r, c_i)  64 MB
__device__ float2 g_hin[BG*NSUB*NN];   // subchunk input states    1 MB

// ---------------- f32x2 helpers ----------------
__device__ __forceinline__ ull pk(float x, float y) {
    ull r; asm("mov.b64 %0, {%1, %2};" : "=l"(r) : "f"(x), "f"(y)); return r;
}
__device__ __forceinline__ void fma2(ull& d, ull a, ull b) {
    asm("fma.rn.f32x2 %0, %1, %2, %0;" : "+l"(d) : "l"(a), "l"(b));
}
__device__ __forceinline__ ull neg2(ull v) { return v ^ 0x8000000080000000ULL; }
__device__ __forceinline__ float comp(ull v, int e) {
    float x, y;
    asm("mov.b64 {%0, %1}, %2;" : "=f"(x), "=f"(y) : "l"(v));
    return e ? y : x;
}
__device__ __forceinline__ float warpsum(float v) {
    #pragma unroll
    for (int off = 16; off; off >>= 1) v += __shfl_xor_sync(0xffffffffu, v, off);
    return v;
}
__device__ __forceinline__ float clampdt(float v) {
    return fminf(fmaxf(v, 1e-4f), 2.0f);
}

// ---------------------------------------------------------------------------
// Kernel 1 (fused projection + local scan). Grid 296, 7 slices per CTA
// (warps 0-6 work, warp 7 idles) -> every SM carries exactly 14 slices.
// Warp owns one (bg, subchunk) slice of 32 tokens; lane owns states l, l+32.
// Weights (wr,wi) packed in smem [d][n]; x register-prefetched per pass and
// staged token-pair interleaved; inner loop = FFMA2 with LDS.64/LDS.128 only.
// ---------------------------------------------------------------------------
__global__ __launch_bounds__(256, 2) void k1_scan(
    const float* __restrict__ xr_g, const float* __restrict__ xi_g,
    const float* __restrict__ logA, const float* __restrict__ Aph_g,
    const float* __restrict__ Bwr,  const float* __restrict__ Bwi,
    const float* __restrict__ dtw_g, const float* __restrict__ dtb_g)
{
    extern __shared__ float sm[];
    float2* wrwi = (float2*)sm;            // [128 d][64 n] (wr,wi)  64 KB
    float*  dtw  = (float*)(wrwi + 8192);  // 512
    float*  nlA  = dtw + 512;              // 512
    float*  aph  = nlA + 512;              // 512
    float2* xbase = (float2*)(aph + 512);  // 8 warps * 512 float2 (32 KB)

    const int tid = threadIdx.x;
    for (int i = tid; i < 8192; i += 256) {
        int d = i >> 6, n = i & 63;
        wrwi[d*64 + n] = make_float2(Bwr[n*128 + d], Bwi[n*128 + d]);
    }
    for (int i = tid; i < 512; i += 256) {
        dtw[i] = dtw_g[i];
        nlA[i] = -log1pf(expf(logA[i]));   // -softplus
        aph[i] = Aph_g[i];
    }
    __syncthreads();

    const int w = tid >> 5, l = tid & 31;
    const int slice = blockIdx.x*7 + w;    // 7 working warps per CTA
    if (w == 7 || slice >= NSLICE) return;
    const int bg = slice >> 6, sub = slice & 63;
    const int b = bg >> 3, g = bg & 7;
    float2* xpr = xbase + w*512;           // [2 t-pairs][128 d] interleaved
    float2* xpi = xpr + 256;
    const float db0 = dtb_g[0], db1 = dtb_g[1];
    const float nlA0 = nlA[g*64 + l],      aph0 = aph[g*64 + l];
    const float nlA1 = nlA[g*64 + l + 32], aph1 = aph[g*64 + l + 32];

    float hr0=0.f, hi0=0.f, cr0=1.f, ci0=0.f;
    float hr1=0.f, hi1=0.f, cr1=1.f, ci1=0.f;

    // prefetch pass 0 x into registers
    float4 pfr[4], pfi[4];
    {
        const int t0 = (b*SS + sub*SUB)*GG + g;
        #pragma unroll
        for (int k = 0; k < 4; ++k) {
            pfr[k] = ((const float4*)(xr_g + (size_t)(t0 + k*GG)*DD))[l];
            pfi[k] = ((const float4*)(xi_g + (size_t)(t0 + k*GG)*DD))[l];
        }
    }

    for (int pass = 0; pass < 8; ++pass) {
        // ---- stage prefetched x token-pair interleaved ----
        #pragma unroll
        for (int p = 0; p < 2; ++p) {
            float4 r0 = pfr[2*p], r1 = pfr[2*p+1];
            float4 i0 = pfi[2*p], i1 = pfi[2*p+1];
            float2* xp = xpr + p*128;
            *(float4*)&xp[4*l]     = make_float4(r0.x, r1.x, r0.y, r1.y);
            *(float4*)&xp[4*l + 2] = make_float4(r0.z, r1.z, r0.w, r1.w);
            float2* xq = xpi + p*128;
            *(float4*)&xq[4*l]     = make_float4(i0.x, i1.x, i0.y, i1.y);
            *(float4*)&xq[4*l + 2] = make_float4(i0.z, i1.z, i0.w, i1.w);
        }
        __syncwarp();

        // ---- prefetch next pass (overlaps with compute below) ----
        if (pass < 7) {
            const int t0 = (b*SS + sub*SUB + (pass+1)*4)*GG + g;
            #pragma unroll
            for (int k = 0; k < 4; ++k) {
                pfr[k] = ((const float4*)(xr_g + (size_t)(t0 + k*GG)*DD))[l];
                pfi[k] = ((const float4*)(xi_g + (size_t)(t0 + k*GG)*DD))[l];
            }
        }

        // ---- dt logits ----
        float dm[4], dp[4];
        #pragma unroll
        for (int p = 0; p < 2; ++p) {
            float a0x=0.f, a0y=0.f, a1x=0.f, a1y=0.f;
            #pragma unroll
            for (int k = 0; k < 4; ++k) {
                int d = l + 32*k;
                float2 xr = xpr[p*128 + d];
                float2 xi = xpi[p*128 + d];
                float w0r = dtw[d], w0i = dtw[128 + d];
                float w1r = dtw[256 + d], w1i = dtw[384 + d];
                a0x = fmaf(xr.x, w0r, fmaf(xi.x, w0i, a0x));
                a0y = fmaf(xr.y, w0r, fmaf(xi.y, w0i, a0y));
                a1x = fmaf(xr.x, w1r, fmaf(xi.x, w1i, a1x));
                a1y = fmaf(xr.y, w1r, fmaf(xi.y, w1i, a1y));
            }
            a0x = warpsum(a0x); a0y = warpsum(a0y);
            a1x = warpsum(a1x); a1y = warpsum(a1y);
            dm[2*p]   = clampdt(__expf(a0x + db0));
            dm[2*p+1] = clampdt(__expf(a0y + db0));
            dp[2*p]   = clampdt(__expf(a1x + db1));
            dp[2*p+1] = clampdt(__expf(a1y + db1));
        }

        // ---- FFMA2 complex B projection ----
        ull aR[2][2] = {{0,0},{0,0}}, aI[2][2] = {{0,0},{0,0}};

        #pragma unroll 8
        for (int d = 0; d < 128; d += 2) {
            float2 wa0 = wrwi[d*64 + l];          // (wr,wi) n=l,    depth d
            float2 wb0 = wrwi[d*64 + l + 32];     // n=l+32, depth d
            float2 wa1 = wrwi[(d+1)*64 + l];
            float2 wb1 = wrwi[(d+1)*64 + l + 32];
            ull ra0 = pk(wa0.x, wa0.x), ia0 = pk(wa0.y, wa0.y);
            ull rb0 = pk(wb0.x, wb0.x), ib0 = pk(wb0.y, wb0.y);
            ull ra1 = pk(wa1.x, wa1.x), ia1 = pk(wa1.y, wa1.y);
            ull rb1 = pk(wb1.x, wb1.x), ib1 = pk(wb1.y, wb1.y);
            ull na0 = neg2(ia0), nb0 = neg2(ib0);
            ull na1 = neg2(ia1), nb1 = neg2(ib1);
            #pragma unroll
            for (int p = 0; p < 2; ++p) {
                ulonglong2 xr = *(const ulonglong2*)(xpr + p*128 + d);
                ulonglong2 xi = *(const ulonglong2*)(xpi + p*128 + d);
                fma2(aR[p][0], xr.x, ra0);  fma2(aR[p][0], xi.x, na0);
                fma2(aI[p][0], xr.x, ia0);  fma2(aI[p][0], xi.x, ra0);
                fma2(aR[p][1], xr.x, rb0);  fma2(aR[p][1], xi.x, nb0);
                fma2(aI[p][1], xr.x, ib0);  fma2(aI[p][1], xi.x, rb0);
                fma2(aR[p][0], xr.y, ra1);  fma2(aR[p][0], xi.y, na1);
                fma2(aI[p][0], xr.y, ia1);  fma2(aI[p][0], xi.y, ra1);
                fma2(aR[p][1], xr.y, rb1);  fma2(aR[p][1], xi.y, nb1);
                fma2(aI[p][1], xr.y, ib1);  fma2(aI[p][1], xi.y, rb1);
            }
        }

        // ---- in-register local scan + store (h_local, cumprod) ----
        const int s0 = sub*SUB + pass*4;
        #pragma unroll
        for (int j = 0; j < 4; ++j) {
            const int p = j >> 1, e = j & 1;
            const float dmv = dm[j], dpv = dp[j];
            const size_t idx = ((size_t)bg*SS + (s0 + j))*NN;
            // slot 0 (n = l)
            {
                float am = __expf(dmv * nlA0);
                float sn, cs; __sincosf(dpv * aph0, &sn, &cs);
                float ar = am*cs, ai = am*sn;
                float br = comp(aR[p][0], e) * dmv;
                float bi = comp(aI[p][0], e) * dmv;
                float nhr = fmaf(ar, hr0, fmaf(-ai, hi0, br));
                float nhi = fmaf(ar, hi0, fmaf( ai, hr0, bi));
                float ncr = ar*cr0 - ai*ci0;
                float nci = ar*ci0 + ai*cr0;
                hr0 = nhr; hi0 = nhi; cr0 = ncr; ci0 = nci;
                g_hc[idx + l] = make_float4(nhr, nhi, ncr, nci);
            }
            // slot 1 (n = l + 32)
            {
                float am = __expf(dmv * nlA1);
                float sn, cs; __sincosf(dpv * aph1, &sn, &cs);
                float ar = am*cs, ai = am*sn;
                float br = comp(aR[p][1], e) * dmv;
                float bi = comp(aI[p][1], e) * dmv;
                float nhr = fmaf(ar, hr1, fmaf(-ai, hi1, br));
                float nhi = fmaf(ar, hi1, fmaf( ai, hr1, bi));
                float ncr = ar*cr1 - ai*ci1;
                float nci = ar*ci1 + ai*cr1;
                hr1 = nhr; hi1 = nhi; cr1 = ncr; ci1 = nci;
                g_hc[idx + l + 32] = make_float4(nhr, nhi, ncr, nci);
            }
        }
        __syncwarp();
    }
}

// ---------------------------------------------------------------------------
// Kernel 2b: sequential subchunk combine; renorm every 8th subchunk boundary.
// ---------------------------------------------------------------------------
__global__ __launch_bounds__(64) void k2b_combine(void)
{
    int bg = blockIdx.x;
    int n = threadIdx.x;
    float hr = 0.f, hi = 0.f;

    float4 ebuf[8];
    #pragma unroll
    for (int j = 0; j < 8; ++j)
        ebuf[j] = g_hc[((size_t)bg*SS + j*SUB + 31)*NN + n];

    for (int s0 = 0; s0 < NSUB; s0 += 8) {
        #pragma unroll
        for (int j = 0; j < 8; ++j) {
            float4 e = ebuf[j];
            int nsub = s0 + 8 + j;
            if (nsub < NSUB)
                ebuf[j] = g_hc[((size_t)bg*SS + nsub*SUB + 31)*NN + n];
            int sub = s0 + j;
            g_hin[(bg*NSUB + sub)*NN + n] = make_float2(hr, hi);
            float nr = fmaf(e.z, hr, fmaf(-e.w, hi, e.x));
            float ni = fmaf(e.z, hi, fmaf( e.w, hr, e.y));
            if ((sub & 7) == 7) {
                float nm = sqrtf(nr*nr + ni*ni + 1e-8f);
                float sc = fminf(nm, 100.0f)/nm;
                nr *= sc; ni *= sc;
            }
            hr = nr; hi = ni;
        }
    }
}

// ---------------------------------------------------------------------------
// Kernel 3: correction h = h_local + c*h_in (+renorm) fused with complex C
// projection. f32x2 packed over OUTPUT d; weight pairs natural LDS.64; h
// staged duplicated (h,h); g_hc register-prefetched per group.
// ---------------------------------------------------------------------------
__global__ __launch_bounds__(256, 2) void k3_out(
    const float* __restrict__ Cwr, const float* __restrict__ Cwi,
    float* __restrict__ out)
{
    extern __shared__ float sm[];
    float* crr = sm;                 // [n][d] 8192 floats (32 KB)
    float* cii = crr + 8192;         // 32 KB
    float2* hbase = (float2*)(cii + 8192);  // 8 warps * 512 float2 (32 KB)

    const int tid = threadIdx.x;
    for (int i = tid; i < 8192; i += 256) {
        int d = i & 127, n = i >> 7;
        crr[n*128 + d] = Cwr[d*64 + n];
        cii[n*128 + d] = Cwi[d*64 + n];
    }
    __syncthreads();

    const int w = tid >> 5, l = tid & 31;
    float2* hrp = hbase + w*512;     // [4 tok][64 n] duplicated (h,h)
    float2* hip = hrp + 256;
    const size_t OFF = (size_t)NTOK*DD;

    // prefetch first group's hc
    float4 pf[8];
    int grp = blockIdx.x;
    if (grp < NTOK/32) {
        #pragma unroll
        for (int k = 0; k < 4; ++k) {
            int t = grp*32 + w*4 + k;
            int b = t >> 14, g = t & 7, s = (t >> 3) & 2047;
            size_t idx = ((size_t)(b*GG + g)*SS + s)*NN;
            pf[2*k]   = g_hc[idx + l];
            pf[2*k+1] = g_hc[idx + l + 32];
        }
    }

    for (; grp < NTOK/32; grp += gridDim.x) {
        const int tbase = grp*32 + w*4;

        // ---- stage corrected h as duplicated pairs ----
        #pragma unroll
        for (int k = 0; k < 4; ++k) {
            int t = tbase + k;
            int b = t >> 14, g = t & 7, s = (t >> 3) & 2047;
            int bg = b*GG + g;
            int hini = (bg*NSUB + (s >> 5))*NN;
            bool renorm = ((s & 255) == 255);
            #pragma unroll
            for (int ns = 0; ns < 2; ++ns) {
                int n = l + 32*ns;
                float4 hc = pf[2*k + ns];
                float2 hin = g_hin[hini + n];
                float hrv = fmaf(hc.z, hin.x, fmaf(-hc.w, hin.y, hc.x));
                float hiv = fmaf(hc.z, hin.y, fmaf( hc.w, hin.x, hc.y));
                if (renorm) {
                    float nm = sqrtf(hrv*hrv + hiv*hiv + 1e-8f);
                    float sc = fminf(nm, 100.0f)/nm;
                    hrv *= sc; hiv *= sc;
                }
                hrp[k*64 + n] = make_float2(hrv, hrv);
                hip[k*64 + n] = make_float2(hiv, hiv);
            }
        }
        __syncwarp();

        // ---- prefetch next group's hc (overlaps compute) ----
        int ngrp = grp + gridDim.x;
        if (ngrp < NTOK/32) {
            #pragma unroll
            for (int k = 0; k < 4; ++k) {
                int t = ngrp*32 + w*4 + k;
                int b = t >> 14, g = t & 7, s = (t >> 3) & 2047;
                size_t idx = ((size_t)(b*GG + g)*SS + s)*NN;
                pf[2*k]   = g_hc[idx + l];
                pf[2*k+1] = g_hc[idx + l + 32];
            }
        }

        // ---- FFMA2 C projection, packed over d ----
        ull yR0[4] = {0,0,0,0}, yR1[4] = {0,0,0,0};
        ull yI0[4] = {0,0,0,0}, yI1[4] = {0,0,0,0};

        #pragma unroll 4
        for (int n = 0; n < NN; ++n) {
            ull cr0 = *(const ull*)&crr[n*128 + 2*l];        // (c[2l],c[2l+1])
            ull cr1 = *(const ull*)&crr[n*128 + 2*l + 64];
            ull ci0 = *(const ull*)&cii[n*128 + 2*l];
            ull ci1 = *(const ull*)&cii[n*128 + 2*l + 64];
            ull nci0 = neg2(ci0), nci1 = neg2(ci1);
            #pragma unroll
            for (int t = 0; t < 4; ++t) {
                ull hr = *(const ull*)&hrp[t*64 + n];        // broadcast
                ull hi = *(const ull*)&hip[t*64 + n];
                fma2(yR0[t], hr, cr0);  fma2(yR0[t], hi, nci0);
                fma2(yI0[t], hr, ci0);  fma2(yI0[t], hi, cr0);
                fma2(yR1[t], hr, cr1);  fma2(yR1[t], hi, nci1);
                fma2(yI1[t], hr, ci1);  fma2(yI1[t], hi, cr1);
            }
        }

        // ---- output: each ull is a float2 of adjacent d ----
        #pragma unroll
        for (int t = 0; t < 4; ++t) {
            size_t o = (size_t)(tbase + t)*DD + 2*l;
            *(ull*)(out + o)            = yR0[t];
            *(ull*)(out + o + 64)       = yR1[t];
            *(ull*)(out + OFF + o)      = yI0[t];
            *(ull*)(out + OFF + o + 64) = yI1[t];
        }
        __syncwarp();
    }
}

// ---------------------------------------------------------------------------
extern "C" void kernel_launch(void* const* d_in, const int* in_sizes, int n_in,
                              void* d_out, int out_size)
{
    const float* x_r  = (const float*)d_in[0];
    const float* x_i  = (const float*)d_in[1];
    const float* logA = (const float*)d_in[2];
    const float* Aph  = (const float*)d_in[3];
    const float* Bwr  = (const float*)d_in[4];
    const float* Bwi  = (const float*)d_in[5];
    const float* Cwr  = (const float*)d_in[6];
    const float* Cwi  = (const float*)d_in[7];
    const float* dtw  = (const float*)d_in[8];
    const float* dtb  = (const float*)d_in[9];
    float* out = (float*)d_out;

    const int smem1 = (8192*2 + 512*3 + 8*512*2) * 4;  // 104448 B
    const int smem3 = (8192*2 + 8*512*2) * 4;          // 98304 B
    cudaFuncSetAttribute(k1_scan, cudaFuncAttributeMaxDynamicSharedMemorySize, smem1);
    cudaFuncSetAttribute(k3_out,  cudaFuncAttributeMaxDynamicSharedMemorySize, smem3);

    k1_scan<<<296, 256, smem1>>>(x_r, x_i, logA, Aph, Bwr, Bwi, dtw, dtb);
    k2b_combine<<<BG, 64>>>();
    k3_out<<<296, 256, smem3>>>(Cwr, Cwi, out);
}

// round 7
// speedup vs baseline: 1.5714x; 1.2064x over previous
#include <cuda_runtime.h>
#include <math.h>
#include <stdint.h>

// Fixed problem shapes
#define BB   4
#define SS   2048
#define GG   8
#define DD   128
#define NN   64
#define BG   (BB*GG)          // 32
#define NTOK (BB*SS*GG)       // 65536
#define SUB  32
#define NSUB (SS/SUB)         // 64

// Scratch (device globals; no allocation allowed)
__device__ float4 g_ab[BG*SS*NN];      // (a_r, a_i, bxr*dt, bxi*dt)  64 MB
__device__ float4 g_hc[BG*SS*NN];      // (hl_r, hl_i, c_r, c_i)      64 MB
__device__ float2 g_hin[BG*NSUB*NN];   // subchunk input states        1 MB

// ---------------- helpers ----------------
__device__ __forceinline__ uint32_t cvt_tf32(float f) {
    uint32_t u; asm("cvt.rna.tf32.f32 %0, %1;" : "=r"(u) : "f"(f)); return u;
}
__device__ __forceinline__ float tf32f(float f) {
    return __uint_as_float(cvt_tf32(f));
}
__device__ __forceinline__ void mma8(float* c, uint32_t a0, uint32_t a1,
                                     uint32_t a2, uint32_t a3,
                                     uint32_t b0, uint32_t b1) {
    asm("mma.sync.aligned.m16n8k8.row.col.f32.tf32.tf32.f32 "
        "{%0,%1,%2,%3}, {%4,%5,%6,%7}, {%8,%9}, {%0,%1,%2,%3};"
        : "+f"(c[0]), "+f"(c[1]), "+f"(c[2]), "+f"(c[3])
        : "r"(a0), "r"(a1), "r"(a2), "r"(a3), "r"(b0), "r"(b1));
}
__device__ __forceinline__ float clampdt(float v) {
    return fminf(fmaxf(v, 1e-4f), 2.0f);
}
// packed column position: pairs (k, k+4) adjacent for LDS.64 fragment loads
__device__ __forceinline__ int unpos(int c) {
    int slot = c & 7;
    return (c & ~7) + (slot >> 1) + ((slot & 1) << 2);
}
__device__ __forceinline__ int posf(int k) {
    return (k & ~7) + ((k & 3) << 1) + ((k & 4) >> 2);
}
// exp(z) on [-2.75, 0.05]: Taylor deg-10 about -1.375 (abs err < 1e-6)
__device__ __forceinline__ float pexp(float z) {
    const float t = z + 1.375f;
    float r = 6.96758145405495e-08f;
    r = fmaf(r, t, 6.96758145405495e-07f);
    r = fmaf(r, t, 6.27082330864946e-06f);
    r = fmaf(r, t, 5.01665864691957e-05f);
    r = fmaf(r, t, 3.51166105284370e-04f);
    r = fmaf(r, t, 2.10699663170622e-03f);
    r = fmaf(r, t, 1.05349831585311e-02f);
    r = fmaf(r, t, 4.21399326341243e-02f);
    r = fmaf(r, t, 1.26419797902373e-01f);
    r = fmaf(r, t, 2.52839595804746e-01f);
    r = fmaf(r, t, 2.52839595804746e-01f);
    return r;
}
// sin/cos Taylor, |w| <= 2 (abs err < 2e-6)
__device__ __forceinline__ void psincos(float w, float& s, float& c) {
    float w2 = w * w;
    float sr = -2.50521083854417e-08f;
    sr = fmaf(sr, w2, 2.75573192239859e-06f);
    sr = fmaf(sr, w2, -1.98412698412698e-04f);
    sr = fmaf(sr, w2, 8.33333333333333e-03f);
    sr = fmaf(sr, w2, -1.66666666666667e-01f);
    s = fmaf(sr * w2, w, w);
    float cr = 2.08767569878681e-09f;
    cr = fmaf(cr, w2, -2.75573192239859e-07f);
    cr = fmaf(cr, w2, 2.48015873015873e-05f);
    cr = fmaf(cr, w2, -1.38888888888889e-03f);
    cr = fmaf(cr, w2, 4.16666666666667e-02f);
    cr = fmaf(cr, w2, -5.0e-01f);
    c = fmaf(cr, w2, 1.0f);
}

// ---------------------------------------------------------------------------
// Kernel 1: tf32 MMA projection. Warp = 16 tokens (2 s x 8 g). B in smem:
//   BRp[72][136]: rows 0..63 = Bwr[n][k], rows 64/65 = dtw[0/1][k<128]
//   BIp[72][136]: rows 0..63 = Bwi[n][k], rows 64/65 = dtw[0/1][k>=128]
// Columns are k-pair packed (k, k+4 adjacent); pitch 136 (mod 32 == 8) makes
// the B-fragment LDS.64 bank-conflict-free. Complex combine via sign-XOR.
// dt logits = 9th N-tile of the real pass (no negation). Epilogue: poly
// exp/sincos for A, write g_ab.
// ---------------------------------------------------------------------------
__global__ __launch_bounds__(256, 2) void k1_mma(
    const float* __restrict__ xr_g, const float* __restrict__ xi_g,
    const float* __restrict__ logA, const float* __restrict__ Aph_g,
    const float* __restrict__ Bwr,  const float* __restrict__ Bwi,
    const float* __restrict__ dtw_g, const float* __restrict__ dtb_g)
{
    extern __shared__ float sm[];
    float* BRp = sm;                 // [72][136]
    float* BIp = BRp + 72*136;       // [72][136]
    float* nlA = BIp + 72*136;       // [512]
    float* aph = nlA + 512;          // [512]

    const int tid = threadIdx.x;
    for (int idx = tid; idx < 72*136; idx += 256) {
        int r = idx / 136, c = idx - r*136;
        float vr = 0.f, vi = 0.f;
        if (c < 128 && r < 66) {
            int k = unpos(c);
            if (r < 64)      { vr = Bwr[r*128 + k];   vi = Bwi[r*128 + k]; }
            else if (r == 64){ vr = dtw_g[k];         vi = dtw_g[128 + k]; }
            else             { vr = dtw_g[256 + k];   vi = dtw_g[384 + k]; }
        }
        BRp[idx] = tf32f(vr);
        BIp[idx] = tf32f(vi);
    }
    for (int i = tid; i < 512; i += 256) {
        nlA[i] = -log1pf(expf(logA[i]));   // -softplus
        aph[i] = Aph_g[i];
    }
    __syncthreads();

    const int w = tid >> 5, l = tid & 31;
    const int q = l >> 2, j = l & 3;
    const int tau0 = (blockIdx.x*8 + w)*16;
    const int b = tau0 >> 14;
    const int s0 = (tau0 >> 3) & 2047;

    float cr[9][4], ci[8][4];
    #pragma unroll
    for (int t = 0; t < 9; ++t) { cr[t][0]=0.f; cr[t][1]=0.f; cr[t][2]=0.f; cr[t][3]=0.f; }
    #pragma unroll
    for (int t = 0; t < 8; ++t) { ci[t][0]=0.f; ci[t][1]=0.f; ci[t][2]=0.f; ci[t][3]=0.f; }

    const size_t rowA = (size_t)(tau0 + q)*128;
    const size_t rowB = (size_t)(tau0 + q + 8)*128;

    // ---- xr half: Bx_r += xr*Bwr ; Bx_i += xr*Bwi ; dt += xr*dtw[:,k<128]
    #pragma unroll 2
    for (int ks = 0; ks < 16; ++ks) {
        const int kk = ks*8 + j;
        uint32_t a0 = cvt_tf32(xr_g[rowA + kk]);
        uint32_t a1 = cvt_tf32(xr_g[rowB + kk]);
        uint32_t a2 = cvt_tf32(xr_g[rowA + kk + 4]);
        uint32_t a3 = cvt_tf32(xr_g[rowB + kk + 4]);
        const int kc = ks*8 + 2*j;
        #pragma unroll
        for (int nt = 0; nt < 9; ++nt) {
            uint2 bb = *(const uint2*)&BRp[(nt*8 + q)*136 + kc];
            mma8(cr[nt], a0, a1, a2, a3, bb.x, bb.y);
        }
        #pragma unroll
        for (int nt = 0; nt < 8; ++nt) {
            uint2 bb = *(const uint2*)&BIp[(nt*8 + q)*136 + kc];
            mma8(ci[nt], a0, a1, a2, a3, bb.x, bb.y);
        }
    }
    // ---- xi half: Bx_r -= xi*Bwi ; Bx_i += xi*Bwr ; dt += xi*dtw[:,k>=128]
    #pragma unroll 2
    for (int ks = 0; ks < 16; ++ks) {
        const int kk = ks*8 + j;
        uint32_t a0 = cvt_tf32(xi_g[rowA + kk]);
        uint32_t a1 = cvt_tf32(xi_g[rowB + kk]);
        uint32_t a2 = cvt_tf32(xi_g[rowA + kk + 4]);
        uint32_t a3 = cvt_tf32(xi_g[rowB + kk + 4]);
        const int kc = ks*8 + 2*j;
        #pragma unroll
        for (int nt = 0; nt < 9; ++nt) {
            uint2 bb = *(const uint2*)&BIp[(nt*8 + q)*136 + kc];
            uint32_t m = (nt < 8) ? 0x80000000u : 0u;   // -Bwi, but +dtw
            mma8(cr[nt], a0, a1, a2, a3, bb.x ^ m, bb.y ^ m);
        }
        #pragma unroll
        for (int nt = 0; nt < 8; ++nt) {
            uint2 bb = *(const uint2*)&BRp[(nt*8 + q)*136 + kc];
            mma8(ci[nt], a0, a1, a2, a3, bb.x, bb.y);
        }
    }

    // ---- epilogue: dt via shfl, A via poly, write g_ab ----
    const float db0 = dtb_g[0], db1 = dtb_g[1];
    const int src = l & ~3;   // lane with j==0 in this group
    float dmL = __shfl_sync(0xffffffffu, cr[8][0], src);
    float dpL = __shfl_sync(0xffffffffu, cr[8][1], src);
    float dmH = __shfl_sync(0xffffffffu, cr[8][2], src);
    float dpH = __shfl_sync(0xffffffffu, cr[8][3], src);
    dmL = clampdt(__expf(dmL + db0));  dpL = clampdt(__expf(dpL + db1));
    dmH = clampdt(__expf(dmH + db0));  dpH = clampdt(__expf(dpH + db1));

    // token q: (b, g=q, s=s0); token q+8: (b, g=q, s=s0+1)
    const size_t idxL = ((size_t)(b*8 + q)*2048 + s0)*64;
    const size_t idxH = idxL + 64;

    #pragma unroll
    for (int nt = 0; nt < 8; ++nt) {
        int n0 = nt*8 + 2*j;
        float nl0 = nlA[q*64 + n0], nl1 = nlA[q*64 + n0 + 1];
        float ap0 = aph[q*64 + n0], ap1 = aph[q*64 + n0 + 1];
        float am, sn, cs;
        am = pexp(dmL*nl0); psincos(dpL*ap0, sn, cs);
        g_ab[idxL + n0]     = make_float4(am*cs, am*sn, cr[nt][0]*dmL, ci[nt][0]*dmL);
        am = pexp(dmL*nl1); psincos(dpL*ap1, sn, cs);
        g_ab[idxL + n0 + 1] = make_float4(am*cs, am*sn, cr[nt][1]*dmL, ci[nt][1]*dmL);
        am = pexp(dmH*nl0); psincos(dpH*ap0, sn, cs);
        g_ab[idxH + n0]     = make_float4(am*cs, am*sn, cr[nt][2]*dmH, ci[nt][2]*dmH);
        am = pexp(dmH*nl1); psincos(dpH*ap1, sn, cs);
        g_ab[idxH + n0 + 1] = make_float4(am*cs, am*sn, cr[nt][3]*dmH, ci[nt][3]*dmH);
    }
}

// ---------------------------------------------------------------------------
// Kernel 2a: per-subchunk (32 tokens) local scan from 0; store (h_local, c).
// ---------------------------------------------------------------------------
__global__ __launch_bounds__(64) void k2a_sub(void)
{
    int blk = blockIdx.x;                 // 0..2047
    int bg = blk >> 6, sub = blk & 63;
    int n = threadIdx.x;
    size_t base = ((size_t)bg*SS + sub*SUB)*NN + n;

    float hr = 0.f, hi = 0.f, cr = 1.f, ci = 0.f;
    float4 buf[8];
    #pragma unroll
    for (int jj = 0; jj < 8; ++jj) buf[jj] = g_ab[base + (size_t)jj*NN];

    #pragma unroll
    for (int t0 = 0; t0 < SUB; t0 += 8) {
        #pragma unroll
        for (int jj = 0; jj < 8; ++jj) {
            float4 a = buf[jj];
            int tn = t0 + 8 + jj;
            if (tn < SUB) buf[jj] = g_ab[base + (size_t)tn*NN];
            float nr = fmaf(a.x, hr, fmaf(-a.y, hi, a.z));
            float ni = fmaf(a.x, hi, fmaf( a.y, hr, a.w));
            hr = nr; hi = ni;
            float qr = a.x*cr - a.y*ci;
            float qi = a.x*ci + a.y*cr;
            cr = qr; ci = qi;
            g_hc[base + (size_t)(t0 + jj)*NN] = make_float4(hr, hi, cr, ci);
        }
    }
}

// ---------------------------------------------------------------------------
// Kernel 2b: sequential subchunk combine; renorm every 8th subchunk boundary.
// ---------------------------------------------------------------------------
__global__ __launch_bounds__(64) void k2b_combine(void)
{
    int bg = blockIdx.x;
    int n = threadIdx.x;
    float hr = 0.f, hi = 0.f;

    float4 ebuf[8];
    #pragma unroll
    for (int jj = 0; jj < 8; ++jj)
        ebuf[jj] = g_hc[((size_t)bg*SS + jj*SUB + 31)*NN + n];

    for (int s0 = 0; s0 < NSUB; s0 += 8) {
        #pragma unroll
        for (int jj = 0; jj < 8; ++jj) {
            float4 e = ebuf[jj];
            int nsub = s0 + 8 + jj;
            if (nsub < NSUB)
                ebuf[jj] = g_hc[((size_t)bg*SS + nsub*SUB + 31)*NN + n];
            int sub = s0 + jj;
            g_hin[(bg*NSUB + sub)*NN + n] = make_float2(hr, hi);
            float nr = fmaf(e.z, hr, fmaf(-e.w, hi, e.x));
            float ni = fmaf(e.z, hi, fmaf( e.w, hr, e.y));
            if ((sub & 7) == 7) {
                float nm = sqrtf(nr*nr + ni*ni + 1e-8f);
                float sc = fminf(nm, 100.0f)/nm;
                nr *= sc; ni *= sc;
            }
            hr = nr; hi = ni;
        }
    }
}

// ---------------------------------------------------------------------------
// Kernel 3: correction h = hl + c*hin (+renorm), then tf32 MMA C-projection.
// CTA = 128 tokens; warp = 16 tokens. A = [hr|hi] (K=128) staged k-packed in
// smem (pre-converted tf32). Two logical passes share fragments: pass-r B =
// [Cwr; -Cwi], pass-i B = [Cwi; Cwr] -- handled by array select + sign XOR.
// C fragments land in natural (token, d) layout -> direct float2 STG.
// ---------------------------------------------------------------------------
__global__ __launch_bounds__(256, 1) void k3_mma(
    const float* __restrict__ Cwr, const float* __restrict__ Cwi,
    float* __restrict__ out)
{
    extern __shared__ float sm[];
    float* P  = sm;             // [128 d][72]  Cwr, k-pair packed
    float* Q  = P + 128*72;     // [128 d][72]  Cwi
    float* hs = Q + 128*72;     // [128 tok][136]  [hr | hi], k-pair packed

    const int tid = threadIdx.x;
    for (int idx = tid; idx < 128*72; idx += 256) {
        int d = idx / 72, c = idx - d*72;
        float vp = 0.f, vq = 0.f;
        if (c < 64) {
            int k = unpos(c);
            vp = Cwr[d*64 + k];
            vq = Cwi[d*64 + k];
        }
        P[idx] = tf32f(vp);
        Q[idx] = tf32f(vq);
    }

    // ---- correction prologue: 128 tok x 64 n ----
    const int tau_base = blockIdx.x*128;
    for (int cell = tid; cell < 128*64; cell += 256) {
        int tl = cell >> 6, n = cell & 63;
        int tau = tau_base + tl;
        int b = tau >> 14, g = tau & 7, s = (tau >> 3) & 2047;
        int bg = b*8 + g;
        float4 hc = g_hc[((size_t)bg*2048 + s)*64 + n];
        float2 hin = g_hin[(bg*64 + (s >> 5))*64 + n];
        float hr = fmaf(hc.z, hin.x, fmaf(-hc.w, hin.y, hc.x));
        float hi = fmaf(hc.z, hin.y, fmaf( hc.w, hin.x, hc.y));
        if ((s & 255) == 255) {
            float nm = sqrtf(hr*hr + hi*hi + 1e-8f);
            float sc = fminf(nm, 100.0f)/nm;
            hr *= sc; hi *= sc;
        }
        int pos = posf(n);
        hs[tl*136 + pos]      = tf32f(hr);
        hs[tl*136 + 64 + pos] = tf32f(hi);
    }
    __syncthreads();

    const int w = tid >> 5, l = tid & 31;
    const int q = l >> 2, j = l & 3;
    const int row0 = w*16 + q;

    float yR[16][4], yI[16][4];
    #pragma unroll
    for (int t = 0; t < 16; ++t) {
        yR[t][0]=0.f; yR[t][1]=0.f; yR[t][2]=0.f; yR[t][3]=0.f;
        yI[t][0]=0.f; yI[t][1]=0.f; yI[t][2]=0.f; yI[t][3]=0.f;
    }

    // ---- hr half (k < 64): y_r += hr*Cwr ; y_i += hr*Cwi ----
    #pragma unroll 2
    for (int ks = 0; ks < 8; ++ks) {
        uint2 aa0 = *(const uint2*)&hs[row0*136 + ks*8 + 2*j];
        uint2 aa1 = *(const uint2*)&hs[(row0 + 8)*136 + ks*8 + 2*j];
        const int kc = ks*8 + 2*j;
        #pragma unroll
        for (int nt = 0; nt < 16; ++nt) {
            uint2 br = *(const uint2*)&P[(nt*8 + q)*72 + kc];
            mma8(yR[nt], aa0.x, aa1.x, aa0.y, aa1.y, br.x, br.y);
            uint2 bi = *(const uint2*)&Q[(nt*8 + q)*72 + kc];
            mma8(yI[nt], aa0.x, aa1.x, aa0.y, aa1.y, bi.x, bi.y);
        }
    }
    // ---- hi half (k >= 64): y_r -= hi*Cwi ; y_i += hi*Cwr ----
    #pragma unroll 2
    for (int ks = 0; ks < 8; ++ks) {
        uint2 aa0 = *(const uint2*)&hs[row0*136 + 64 + ks*8 + 2*j];
        uint2 aa1 = *(const uint2*)&hs[(row0 + 8)*136 + 64 + ks*8 + 2*j];
        const int kc = ks*8 + 2*j;
        #pragma unroll
        for (int nt = 0; nt < 16; ++nt) {
            uint2 br = *(const uint2*)&Q[(nt*8 + q)*72 + kc];
            mma8(yR[nt], aa0.x, aa1.x, aa0.y, aa1.y,
                 br.x ^ 0x80000000u, br.y ^ 0x80000000u);
            uint2 bi = *(const uint2*)&P[(nt*8 + q)*72 + kc];
            mma8(yI[nt], aa0.x, aa1.x, aa0.y, aa1.y, bi.x, bi.y);
        }
    }

    // ---- output ----
    const size_t OFF = (size_t)NTOK*128;
    #pragma unroll
    for (int nt = 0; nt < 16; ++nt) {
        int d0 = nt*8 + 2*j;
        size_t tA = (size_t)(tau_base + row0)*128 + d0;
        size_t tB = (size_t)(tau_base + row0 + 8)*128 + d0;
        *(float2*)&out[tA]       = make_float2(yR[nt][0], yR[nt][1]);
        *(float2*)&out[tB]       = make_float2(yR[nt][2], yR[nt][3]);
        *(float2*)&out[OFF + tA] = make_float2(yI[nt][0], yI[nt][1]);
        *(float2*)&out[OFF + tB] = make_float2(yI[nt][2], yI[nt][3]);
    }
}

// ---------------------------------------------------------------------------
extern "C" void kernel_launch(void* const* d_in, const int* in_sizes, int n_in,
                              void* d_out, int out_size)
{
    const float* x_r  = (const float*)d_in[0];
    const float* x_i  = (const float*)d_in[1];
    const float* logA = (const float*)d_in[2];
    const float* Aph  = (const float*)d_in[3];
    const float* Bwr  = (const float*)d_in[4];
    const float* Bwi  = (const float*)d_in[5];
    const float* Cwr  = (const float*)d_in[6];
    const float* Cwi  = (const float*)d_in[7];
    const float* dtw  = (const float*)d_in[8];
    const float* dtb  = (const float*)d_in[9];
    float* out = (float*)d_out;

    const int smem1 = (72*136*2 + 1024) * 4;          // 82,432 B
    const int smem3 = (128*72*2 + 128*136) * 4;       // 143,360 B
    cudaFuncSetAttribute(k1_mma, cudaFuncAttributeMaxDynamicSharedMemorySize, smem1);
    cudaFuncSetAttribute(k3_mma, cudaFuncAttributeMaxDynamicSharedMemorySize, smem3);

    k1_mma<<<512, 256, smem1>>>(x_r, x_i, logA, Aph, Bwr, Bwi, dtw, dtb);
    k2a_sub<<<BG*NSUB, 64>>>();
    k2b_combine<<<BG, 64>>>();
    k3_mma<<<512, 256, smem3>>>(Cwr, Cwi, out);
}

// round 8
// speedup vs baseline: 1.7184x; 1.0935x over previous
#include <cuda_runtime.h>
#include <math.h>
#include <stdint.h>

// Fixed problem shapes
#define BB   4
#define SS   2048
#define GG   8
#define DD   128
#define NN   64
#define BG   (BB*GG)          // 32
#define NTOK (BB*SS*GG)       // 65536
#define SUB  32
#define NSUB (SS/SUB)         // 64

// Scratch (device globals; no allocation allowed)
__device__ float4 g_ab[BG*SS*NN];      // (a_r, a_i, bxr*dt, bxi*dt)  64 MB
__device__ float4 g_hc[BG*SS*NN];      // (hl_r, hl_i, c_r, c_i)      64 MB
__device__ float2 g_hin[BG*NSUB*NN];   // subchunk input states        1 MB

// ---------------- helpers ----------------
__device__ __forceinline__ uint32_t cvt_tf32(float f) {
    uint32_t u; asm("cvt.rna.tf32.f32 %0, %1;" : "=r"(u) : "f"(f)); return u;
}
__device__ __forceinline__ float tf32f(float f) {
    return __uint_as_float(cvt_tf32(f));
}
__device__ __forceinline__ void mma8(float* c, uint32_t a0, uint32_t a1,
                                     uint32_t a2, uint32_t a3,
                                     uint32_t b0, uint32_t b1) {
    asm("mma.sync.aligned.m16n8k8.row.col.f32.tf32.tf32.f32 "
        "{%0,%1,%2,%3}, {%4,%5,%6,%7}, {%8,%9}, {%0,%1,%2,%3};"
        : "+f"(c[0]), "+f"(c[1]), "+f"(c[2]), "+f"(c[3])
        : "r"(a0), "r"(a1), "r"(a2), "r"(a3), "r"(b0), "r"(b1));
}
__device__ __forceinline__ float clampdt(float v) {
    return fminf(fmaxf(v, 1e-4f), 2.0f);
}
// packed column position: pairs (k, k+4) adjacent for LDS.64 fragment loads
__device__ __forceinline__ int unpos(int c) {
    int slot = c & 7;
    return (c & ~7) + (slot >> 1) + ((slot & 1) << 2);
}
__device__ __forceinline__ int posf(int k) {
    return (k & ~7) + ((k & 3) << 1) + ((k & 4) >> 2);
}
// exp(z) on [-2.75, 0.05]: Taylor deg-10 about -1.375 (abs err < 1e-6)
__device__ __forceinline__ float pexp(float z) {
    const float t = z + 1.375f;
    float r = 6.96758145405495e-08f;
    r = fmaf(r, t, 6.96758145405495e-07f);
    r = fmaf(r, t, 6.27082330864946e-06f);
    r = fmaf(r, t, 5.01665864691957e-05f);
    r = fmaf(r, t, 3.51166105284370e-04f);
    r = fmaf(r, t, 2.10699663170622e-03f);
    r = fmaf(r, t, 1.05349831585311e-02f);
    r = fmaf(r, t, 4.21399326341243e-02f);
    r = fmaf(r, t, 1.26419797902373e-01f);
    r = fmaf(r, t, 2.52839595804746e-01f);
    r = fmaf(r, t, 2.52839595804746e-01f);
    return r;
}
// sin/cos Taylor, |w| <= 2 (abs err < 2e-6)
__device__ __forceinline__ void psincos(float w, float& s, float& c) {
    float w2 = w * w;
    float sr = -2.50521083854417e-08f;
    sr = fmaf(sr, w2, 2.75573192239859e-06f);
    sr = fmaf(sr, w2, -1.98412698412698e-04f);
    sr = fmaf(sr, w2, 8.33333333333333e-03f);
    sr = fmaf(sr, w2, -1.66666666666667e-01f);
    s = fmaf(sr * w2, w, w);
    float cr = 2.08767569878681e-09f;
    cr = fmaf(cr, w2, -2.75573192239859e-07f);
    cr = fmaf(cr, w2, 2.48015873015873e-05f);
    cr = fmaf(cr, w2, -1.38888888888889e-03f);
    cr = fmaf(cr, w2, 4.16666666666667e-02f);
    cr = fmaf(cr, w2, -5.0e-01f);
    c = fmaf(cr, w2, 1.0f);
}

// ---------------------------------------------------------------------------
// Kernel 1: tf32 MMA projection (unchanged from R7). Warp = 16 tokens.
// ---------------------------------------------------------------------------
__global__ __launch_bounds__(256, 2) void k1_mma(
    const float* __restrict__ xr_g, const float* __restrict__ xi_g,
    const float* __restrict__ logA, const float* __restrict__ Aph_g,
    const float* __restrict__ Bwr,  const float* __restrict__ Bwi,
    const float* __restrict__ dtw_g, const float* __restrict__ dtb_g)
{
    extern __shared__ float sm[];
    float* BRp = sm;                 // [72][136]
    float* BIp = BRp + 72*136;       // [72][136]
    float* nlA = BIp + 72*136;       // [512]
    float* aph = nlA + 512;          // [512]

    const int tid = threadIdx.x;
    for (int idx = tid; idx < 72*136; idx += 256) {
        int r = idx / 136, c = idx - r*136;
        float vr = 0.f, vi = 0.f;
        if (c < 128 && r < 66) {
            int k = unpos(c);
            if (r < 64)      { vr = Bwr[r*128 + k];   vi = Bwi[r*128 + k]; }
            else if (r == 64){ vr = dtw_g[k];         vi = dtw_g[128 + k]; }
            else             { vr = dtw_g[256 + k];   vi = dtw_g[384 + k]; }
        }
        BRp[idx] = tf32f(vr);
        BIp[idx] = tf32f(vi);
    }
    for (int i = tid; i < 512; i += 256) {
        nlA[i] = -log1pf(expf(logA[i]));   // -softplus
        aph[i] = Aph_g[i];
    }
    __syncthreads();

    const int w = tid >> 5, l = tid & 31;
    const int q = l >> 2, j = l & 3;
    const int tau0 = (blockIdx.x*8 + w)*16;
    const int b = tau0 >> 14;
    const int s0 = (tau0 >> 3) & 2047;

    float cr[9][4], ci[8][4];
    #pragma unroll
    for (int t = 0; t < 9; ++t) { cr[t][0]=0.f; cr[t][1]=0.f; cr[t][2]=0.f; cr[t][3]=0.f; }
    #pragma unroll
    for (int t = 0; t < 8; ++t) { ci[t][0]=0.f; ci[t][1]=0.f; ci[t][2]=0.f; ci[t][3]=0.f; }

    const size_t rowA = (size_t)(tau0 + q)*128;
    const size_t rowB = (size_t)(tau0 + q + 8)*128;

    // ---- xr half: Bx_r += xr*Bwr ; Bx_i += xr*Bwi ; dt += xr*dtw[:,k<128]
    #pragma unroll 2
    for (int ks = 0; ks < 16; ++ks) {
        const int kk = ks*8 + j;
        uint32_t a0 = cvt_tf32(xr_g[rowA + kk]);
        uint32_t a1 = cvt_tf32(xr_g[rowB + kk]);
        uint32_t a2 = cvt_tf32(xr_g[rowA + kk + 4]);
        uint32_t a3 = cvt_tf32(xr_g[rowB + kk + 4]);
        const int kc = ks*8 + 2*j;
        #pragma unroll
        for (int nt = 0; nt < 9; ++nt) {
            uint2 bb = *(const uint2*)&BRp[(nt*8 + q)*136 + kc];
            mma8(cr[nt], a0, a1, a2, a3, bb.x, bb.y);
        }
        #pragma unroll
        for (int nt = 0; nt < 8; ++nt) {
            uint2 bb = *(const uint2*)&BIp[(nt*8 + q)*136 + kc];
            mma8(ci[nt], a0, a1, a2, a3, bb.x, bb.y);
        }
    }
    // ---- xi half: Bx_r -= xi*Bwi ; Bx_i += xi*Bwr ; dt += xi*dtw[:,k>=128]
    #pragma unroll 2
    for (int ks = 0; ks < 16; ++ks) {
        const int kk = ks*8 + j;
        uint32_t a0 = cvt_tf32(xi_g[rowA + kk]);
        uint32_t a1 = cvt_tf32(xi_g[rowB + kk]);
        uint32_t a2 = cvt_tf32(xi_g[rowA + kk + 4]);
        uint32_t a3 = cvt_tf32(xi_g[rowB + kk + 4]);
        const int kc = ks*8 + 2*j;
        #pragma unroll
        for (int nt = 0; nt < 9; ++nt) {
            uint2 bb = *(const uint2*)&BIp[(nt*8 + q)*136 + kc];
            uint32_t m = (nt < 8) ? 0x80000000u : 0u;   // -Bwi, but +dtw
            mma8(cr[nt], a0, a1, a2, a3, bb.x ^ m, bb.y ^ m);
        }
        #pragma unroll
        for (int nt = 0; nt < 8; ++nt) {
            uint2 bb = *(const uint2*)&BRp[(nt*8 + q)*136 + kc];
            mma8(ci[nt], a0, a1, a2, a3, bb.x, bb.y);
        }
    }

    // ---- epilogue: dt via shfl, A via poly, write g_ab ----
    const float db0 = dtb_g[0], db1 = dtb_g[1];
    const int src = l & ~3;   // lane with j==0 in this group
    float dmL = __shfl_sync(0xffffffffu, cr[8][0], src);
    float dpL = __shfl_sync(0xffffffffu, cr[8][1], src);
    float dmH = __shfl_sync(0xffffffffu, cr[8][2], src);
    float dpH = __shfl_sync(0xffffffffu, cr[8][3], src);
    dmL = clampdt(__expf(dmL + db0));  dpL = clampdt(__expf(dpL + db1));
    dmH = clampdt(__expf(dmH + db0));  dpH = clampdt(__expf(dpH + db1));

    // token q: (b, g=q, s=s0); token q+8: (b, g=q, s=s0+1)
    const size_t idxL = ((size_t)(b*8 + q)*2048 + s0)*64;
    const size_t idxH = idxL + 64;

    #pragma unroll
    for (int nt = 0; nt < 8; ++nt) {
        int n0 = nt*8 + 2*j;
        float nl0 = nlA[q*64 + n0], nl1 = nlA[q*64 + n0 + 1];
        float ap0 = aph[q*64 + n0], ap1 = aph[q*64 + n0 + 1];
        float am, sn, cs;
        am = pexp(dmL*nl0); psincos(dpL*ap0, sn, cs);
        g_ab[idxL + n0]     = make_float4(am*cs, am*sn, cr[nt][0]*dmL, ci[nt][0]*dmL);
        am = pexp(dmL*nl1); psincos(dpL*ap1, sn, cs);
        g_ab[idxL + n0 + 1] = make_float4(am*cs, am*sn, cr[nt][1]*dmL, ci[nt][1]*dmL);
        am = pexp(dmH*nl0); psincos(dpH*ap0, sn, cs);
        g_ab[idxH + n0]     = make_float4(am*cs, am*sn, cr[nt][2]*dmH, ci[nt][2]*dmH);
        am = pexp(dmH*nl1); psincos(dpH*ap1, sn, cs);
        g_ab[idxH + n0 + 1] = make_float4(am*cs, am*sn, cr[nt][3]*dmH, ci[nt][3]*dmH);
    }
}

// ---------------------------------------------------------------------------
// Kernel 2a: per-subchunk (32 tokens) local scan from 0; store (h_local, c).
// ---------------------------------------------------------------------------
__global__ __launch_bounds__(64) void k2a_sub(void)
{
    int blk = blockIdx.x;                 // 0..2047
    int bg = blk >> 6, sub = blk & 63;
    int n = threadIdx.x;
    size_t base = ((size_t)bg*SS + sub*SUB)*NN + n;

    float hr = 0.f, hi = 0.f, cr = 1.f, ci = 0.f;
    float4 buf[8];
    #pragma unroll
    for (int jj = 0; jj < 8; ++jj) buf[jj] = g_ab[base + (size_t)jj*NN];

    #pragma unroll
    for (int t0 = 0; t0 < SUB; t0 += 8) {
        #pragma unroll
        for (int jj = 0; jj < 8; ++jj) {
            float4 a = buf[jj];
            int tn = t0 + 8 + jj;
            if (tn < SUB) buf[jj] = g_ab[base + (size_t)tn*NN];
            float nr = fmaf(a.x, hr, fmaf(-a.y, hi, a.z));
            float ni = fmaf(a.x, hi, fmaf( a.y, hr, a.w));
            hr = nr; hi = ni;
            float qr = a.x*cr - a.y*ci;
            float qi = a.x*ci + a.y*cr;
            cr = qr; ci = qi;
            g_hc[base + (size_t)(t0 + jj)*NN] = make_float4(hr, hi, cr, ci);
        }
    }
}

// ---------------------------------------------------------------------------
// Kernel 2b: sequential subchunk combine; renorm every 8th subchunk boundary.
// ---------------------------------------------------------------------------
__global__ __launch_bounds__(64) void k2b_combine(void)
{
    int bg = blockIdx.x;
    int n = threadIdx.x;
    float hr = 0.f, hi = 0.f;

    float4 ebuf[8];
    #pragma unroll
    for (int jj = 0; jj < 8; ++jj)
        ebuf[jj] = g_hc[((size_t)bg*SS + jj*SUB + 31)*NN + n];

    for (int s0 = 0; s0 < NSUB; s0 += 8) {
        #pragma unroll
        for (int jj = 0; jj < 8; ++jj) {
            float4 e = ebuf[jj];
            int nsub = s0 + 8 + jj;
            if (nsub < NSUB)
                ebuf[jj] = g_hc[((size_t)bg*SS + nsub*SUB + 31)*NN + n];
            int sub = s0 + jj;
            g_hin[(bg*NSUB + sub)*NN + n] = make_float2(hr, hi);
            float nr = fmaf(e.z, hr, fmaf(-e.w, hi, e.x));
            float ni = fmaf(e.z, hi, fmaf( e.w, hr, e.y));
            if ((sub & 7) == 7) {
                float nm = sqrtf(nr*nr + ni*ni + 1e-8f);
                float sc = fminf(nm, 100.0f)/nm;
                nr *= sc; ni *= sc;
            }
            hr = nr; hi = ni;
        }
    }
}

// ---------------------------------------------------------------------------
// Kernel 3: correction h = hl + c*hin (+renorm), then tf32 MMA C-projection.
// block = 512, CTA = 128 tokens, 16 warps. Warp task = (mrow 0..7: 16 tokens)
// x (half 0..1: yR or yI). Accumulators per lane: 16 tiles x 4 = 64 floats
// (halved vs R7 -> ~95 regs, 16 warps resident). Sign/array select per half:
//   yR: k<64 -> +P, k>=64 -> -Q ;  yI: k<64 -> +Q, k>=64 -> +P
// ---------------------------------------------------------------------------
__global__ __launch_bounds__(512, 1) void k3_mma(
    const float* __restrict__ Cwr, const float* __restrict__ Cwi,
    float* __restrict__ out)
{
    extern __shared__ float sm[];
    float* P  = sm;             // [128 d][72]  Cwr, k-pair packed
    float* Q  = P + 128*72;     // [128 d][72]  Cwi
    float* hs = Q + 128*72;     // [128 tok][136]  [hr | hi], k-pair packed

    const int tid = threadIdx.x;
    for (int idx = tid; idx < 128*72; idx += 512) {
        int d = idx / 72, c = idx - d*72;
        float vp = 0.f, vq = 0.f;
        if (c < 64) {
            int k = unpos(c);
            vp = Cwr[d*64 + k];
            vq = Cwi[d*64 + k];
        }
        P[idx] = tf32f(vp);
        Q[idx] = tf32f(vq);
    }

    // ---- correction prologue: 128 tok x 64 n ----
    const int tau_base = blockIdx.x*128;
    for (int cell = tid; cell < 128*64; cell += 512) {
        int tl = cell >> 6, n = cell & 63;
        int tau = tau_base + tl;
        int b = tau >> 14, g = tau & 7, s = (tau >> 3) & 2047;
        int bg = b*8 + g;
        float4 hc = g_hc[((size_t)bg*2048 + s)*64 + n];
        float2 hin = g_hin[(bg*64 + (s >> 5))*64 + n];
        float hr = fmaf(hc.z, hin.x, fmaf(-hc.w, hin.y, hc.x));
        float hi = fmaf(hc.z, hin.y, fmaf( hc.w, hin.x, hc.y));
        if ((s & 255) == 255) {
            float nm = sqrtf(hr*hr + hi*hi + 1e-8f);
            float sc = fminf(nm, 100.0f)/nm;
            hr *= sc; hi *= sc;
        }
        int pos = posf(n);
        hs[tl*136 + pos]      = tf32f(hr);
        hs[tl*136 + 64 + pos] = tf32f(hi);
    }
    __syncthreads();

    const int w = tid >> 5, l = tid & 31;
    const int q = l >> 2, j = l & 3;
    const int mrow = w & 7;          // which 16-token block
    const int half = w >> 3;         // 0 = yR, 1 = yI
    const int row0 = mrow*16 + q;

    // B-matrix selection per k-half
    const float* Blo = half ? Q : P;     // k < 64
    const float* Bhi = half ? P : Q;     // k >= 64
    const uint32_t mhi = half ? 0u : 0x80000000u;   // negate Q for yR

    float y[16][4];
    #pragma unroll
    for (int t = 0; t < 16; ++t) { y[t][0]=0.f; y[t][1]=0.f; y[t][2]=0.f; y[t][3]=0.f; }

    // ---- hr half (k < 64) ----
    #pragma unroll 2
    for (int ks = 0; ks < 8; ++ks) {
        uint2 aa0 = *(const uint2*)&hs[row0*136 + ks*8 + 2*j];
        uint2 aa1 = *(const uint2*)&hs[(row0 + 8)*136 + ks*8 + 2*j];
        const int kc = ks*8 + 2*j;
        #pragma unroll
        for (int nt = 0; nt < 16; ++nt) {
            uint2 bb = *(const uint2*)&Blo[(nt*8 + q)*72 + kc];
            mma8(y[nt], aa0.x, aa1.x, aa0.y, aa1.y, bb.x, bb.y);
        }
    }
    // ---- hi half (k >= 64) ----
    #pragma unroll 2
    for (int ks = 0; ks < 8; ++ks) {
        uint2 aa0 = *(const uint2*)&hs[row0*136 + 64 + ks*8 + 2*j];
        uint2 aa1 = *(const uint2*)&hs[(row0 + 8)*136 + 64 + ks*8 + 2*j];
        const int kc = ks*8 + 2*j;
        #pragma unroll
        for (int nt = 0; nt < 16; ++nt) {
            uint2 bb = *(const uint2*)&Bhi[(nt*8 + q)*72 + kc];
            mma8(y[nt], aa0.x, aa1.x, aa0.y, aa1.y, bb.x ^ mhi, bb.y ^ mhi);
        }
    }

    // ---- output ----
    float* outh = out + (size_t)half * ((size_t)NTOK*128);
    #pragma unroll
    for (int nt = 0; nt < 16; ++nt) {
        int d0 = nt*8 + 2*j;
        size_t tA = (size_t)(tau_base + row0)*128 + d0;
        size_t tB = (size_t)(tau_base + row0 + 8)*128 + d0;
        *(float2*)&outh[tA] = make_float2(y[nt][0], y[nt][1]);
        *(float2*)&outh[tB] = make_float2(y[nt][2], y[nt][3]);
    }
}

// ---------------------------------------------------------------------------
extern "C" void kernel_launch(void* const* d_in, const int* in_sizes, int n_in,
                              void* d_out, int out_size)
{
    const float* x_r  = (const float*)d_in[0];
    const float* x_i  = (const float*)d_in[1];
    const float* logA = (const float*)d_in[2];
    const float* Aph  = (const float*)d_in[3];
    const float* Bwr  = (const float*)d_in[4];
    const float* Bwi  = (const float*)d_in[5];
    const float* Cwr  = (const float*)d_in[6];
    const float* Cwi  = (const float*)d_in[7];
    const float* dtw  = (const float*)d_in[8];
    const float* dtb  = (const float*)d_in[9];
    float* out = (float*)d_out;

    const int smem1 = (72*136*2 + 1024) * 4;          // 82,432 B
    const int smem3 = (128*72*2 + 128*136) * 4;       // 143,360 B
    cudaFuncSetAttribute(k1_mma, cudaFuncAttributeMaxDynamicSharedMemorySize, smem1);
    cudaFuncSetAttribute(k3_mma, cudaFuncAttributeMaxDynamicSharedMemorySize, smem3);

    k1_mma<<<512, 256, smem1>>>(x_r, x_i, logA, Aph, Bwr, Bwi, dtw, dtb);
    k2a_sub<<<BG*NSUB, 64>>>();
    k2b_combine<<<BG, 64>>>();
    k3_mma<<<512, 512, smem3>>>(Cwr, Cwi, out);
}